// round 13
// baseline (speedup 1.0000x reference)
#include <cuda_runtime.h>
#include <cuda_fp16.h>
#include <math.h>
#include <stdint.h>

#define S_TOK 8192
#define MDIM  1024
#define HDIM  2048
#define EDIM  8
#define CDIM  2048

// ---------------- scratch (device globals; no allocation) ----------------
__device__ int   g_topi[S_TOK * 2];
__device__ float g_gate[S_TOK * 2];
__device__ int   g_dexp[S_TOK * 2];
__device__ int   g_dpos[S_TOK * 2];
__device__ float g_dg  [S_TOK * 2];
__device__ int   g_src [EDIM * CDIM];
__device__ float g_z   [EDIM * CDIM];
__device__ float g_w2s [EDIM * HDIM];
__device__ float g_b2s [EDIM];
// fp16 copies for MMA
__device__ __half g_xh [(size_t)S_TOK * MDIM];
__device__ __half g_w1h[(size_t)EDIM * MDIM * HDIM];

// ---------------- helpers -------------------------------------------------
__device__ __forceinline__ uint32_t smem_u32(const void* p) {
    uint32_t a;
    asm("{ .reg .u64 t; cvta.to.shared.u64 t, %1; cvt.u32.u64 %0, t; }"
        : "=r"(a) : "l"(p));
    return a;
}
#define CP_ASYNC(saddr, gptr) \
    asm volatile("cp.async.cg.shared.global [%0], [%1], 16;" \
        :: "r"(saddr), "l"(gptr) : "memory")
#define CP_ASYNC_Z(saddr, gptr, srcsz) \
    asm volatile("cp.async.cg.shared.global [%0], [%1], 16, %2;" \
        :: "r"(saddr), "l"(gptr), "r"(srcsz) : "memory")
#define CP_COMMIT() asm volatile("cp.async.commit_group;" ::: "memory")
#define CP_WAIT(n)  asm volatile("cp.async.wait_group %0;" :: "n"(n) : "memory")

#define LDSM4(r, addr) \
    asm volatile("ldmatrix.sync.aligned.m8n8.x4.shared.b16 {%0,%1,%2,%3}, [%4];" \
        : "=r"((r)[0]), "=r"((r)[1]), "=r"((r)[2]), "=r"((r)[3]) : "r"(addr))
#define LDSM4T(r, addr) \
    asm volatile("ldmatrix.sync.aligned.m8n8.x4.trans.shared.b16 {%0,%1,%2,%3}, [%4];" \
        : "=r"((r)[0]), "=r"((r)[1]), "=r"((r)[2]), "=r"((r)[3]) : "r"(addr))
#define MMA_F16(d, a, b0, b1) \
    asm volatile("mma.sync.aligned.m16n8k16.row.col.f32.f16.f16.f32 " \
        "{%0,%1,%2,%3}, {%4,%5,%6,%7}, {%8,%9}, {%0,%1,%2,%3};" \
        : "+f"((d)[0]), "+f"((d)[1]), "+f"((d)[2]), "+f"((d)[3]) \
        : "r"((a)[0]), "r"((a)[1]), "r"((a)[2]), "r"((a)[3]), "r"(b0), "r"(b1))

// ---------------- 1. merged prep: w1->fp16 | w2s/b2s | router -------------
// blocks [0, NW4B)               : w1 fp32->fp16 conversion
// blocks [NW4B, NW4B+2049)       : w2s / b2s row reductions
// blocks [NW4B+2049, +1024)      : router (warp per token, emits fp16 x)
#define NW4   (EDIM * MDIM * HDIM / 4)
#define NW4B  (NW4 / 256)
#define RTRB  (S_TOK / 8)
__global__ void fused_prep_kernel(const float* __restrict__ x,
                                  const float* __restrict__ wg,
                                  const float* __restrict__ w1,
                                  const float* __restrict__ w2,
                                  const float* __restrict__ b2) {
    int b = blockIdx.x;
    if (b < NW4B) {                       // ---- w1 conversion ----
        int i = b * 256 + threadIdx.x;
        float4 v = ((const float4*)w1)[i];
        __half2 h01 = __floats2half2_rn(v.x, v.y);
        __half2 h23 = __floats2half2_rn(v.z, v.w);
        ((uint2*)g_w1h)[i] = make_uint2(*(uint32_t*)&h01, *(uint32_t*)&h23);
        return;
    }
    if (b < NW4B + 2049) {                // ---- w2s / b2s ----
        int warp = (b - NW4B) * 8 + (threadIdx.x >> 5);
        int lane = threadIdx.x & 31;
        if (warp < EDIM * HDIM) {
            const float4* r = (const float4*)(w2 + (size_t)warp * MDIM);
            float s = 0.f;
            for (int m = lane; m < MDIM / 4; m += 32) {
                float4 v = r[m];
                s += v.x + v.y + v.z + v.w;
            }
#pragma unroll
            for (int off = 16; off > 0; off >>= 1)
                s += __shfl_down_sync(0xffffffffu, s, off);
            if (lane == 0) g_w2s[warp] = s;
        } else if (warp < EDIM * HDIM + EDIM) {
            int e = warp - EDIM * HDIM;
            const float4* r = (const float4*)(b2 + (size_t)e * MDIM);
            float s = 0.f;
            for (int m = lane; m < MDIM / 4; m += 32) {
                float4 v = r[m];
                s += v.x + v.y + v.z + v.w;
            }
#pragma unroll
            for (int off = 16; off > 0; off >>= 1)
                s += __shfl_down_sync(0xffffffffu, s, off);
            if (lane == 0) g_b2s[e] = s;
        }
        return;
    }
    // ---- router ----
    int tok = (b - NW4B - 2049) * 8 + (threadIdx.x >> 5);
    int lane = threadIdx.x & 31;
    if (tok >= S_TOK) return;
    const float* xr = x + (size_t)tok * MDIM;
    __half* xh = g_xh + (size_t)tok * MDIM;
    float acc[8];
#pragma unroll
    for (int e = 0; e < 8; e++) acc[e] = 0.f;
    for (int m = lane; m < MDIM; m += 32) {
        float xv = xr[m];
        xh[m] = __float2half_rn(xv);
        const float* wr = wg + m * 8;
        float4 w0 = *(const float4*)(wr);
        float4 w1v = *(const float4*)(wr + 4);
        acc[0] += xv * w0.x; acc[1] += xv * w0.y;
        acc[2] += xv * w0.z; acc[3] += xv * w0.w;
        acc[4] += xv * w1v.x; acc[5] += xv * w1v.y;
        acc[6] += xv * w1v.z; acc[7] += xv * w1v.w;
    }
#pragma unroll
    for (int off = 16; off > 0; off >>= 1)
#pragma unroll
        for (int e = 0; e < 8; e++)
            acc[e] += __shfl_down_sync(0xffffffffu, acc[e], off);
    if (lane == 0) {
        float mx = acc[0];
#pragma unroll
        for (int e = 1; e < 8; e++) mx = fmaxf(mx, acc[e]);
        float sc[8], s = 0.f;
#pragma unroll
        for (int e = 0; e < 8; e++) { sc[e] = expf(acc[e] - mx); s += sc[e]; }
        float inv = 1.f / s;
#pragma unroll
        for (int e = 0; e < 8; e++) sc[e] *= inv;
        int i0 = 0;
#pragma unroll
        for (int e = 1; e < 8; e++) if (sc[e] > sc[i0]) i0 = e;
        int i1 = -1;
#pragma unroll
        for (int e = 0; e < 8; e++) {
            if (e == i0) continue;
            if (i1 < 0 || sc[e] > sc[i1]) i1 = e;
        }
        float v0 = sc[i0], v1 = sc[i1];
        float den = 1.f / (v0 + v1 + 1e-9f);
        g_topi[tok * 2 + 0] = i0;
        g_topi[tok * 2 + 1] = i1;
        g_gate[tok * 2 + 0] = v0 * den;
        g_gate[tok * 2 + 1] = v1 * den;
    }
}

// ---------------- 2. ordered scan (512 thr, warp-parallel bin scans) ------
__global__ void scan_kernel() {
    __shared__ int h0[512][9];
    __shared__ int h1[512][9];
    __shared__ int tot0s[8];
    int t = threadIdx.x;
    for (int i = t; i < EDIM * CDIM; i += 512) { g_src[i] = -1; g_z[i] = 0.f; }

    int c0[8], c1[8];
#pragma unroll
    for (int e = 0; e < 8; e++) { c0[e] = 0; c1[e] = 0; }
    int base = t * 16;
    for (int k = 0; k < 16; k++) {
        int s = base + k;
        c0[g_topi[2 * s + 0]]++;
        c1[g_topi[2 * s + 1]]++;
    }
#pragma unroll
    for (int e = 0; e < 8; e++) { h0[t][e] = c0[e]; h1[t][e] = c1[e]; }
    __syncthreads();

    int wid = t >> 5, lane = t & 31;
    if (wid < 16) {
        int e = wid & 7, which = wid >> 3;
        int vals[16], run = 0;
#pragma unroll
        for (int j = 0; j < 16; j++) {
            int v = which ? h1[lane * 16 + j][e] : h0[lane * 16 + j][e];
            vals[j] = run; run += v;
        }
        int tot = run;
#pragma unroll
        for (int off = 1; off < 32; off <<= 1) {
            int n = __shfl_up_sync(0xffffffffu, tot, off);
            if (lane >= off) tot += n;
        }
        int excl = tot - run;
#pragma unroll
        for (int j = 0; j < 16; j++) {
            if (which) h1[lane * 16 + j][e] = vals[j] + excl;
            else       h0[lane * 16 + j][e] = vals[j] + excl;
        }
        if (lane == 31 && which == 0) tot0s[e] = tot;
    }
    __syncthreads();

#pragma unroll
    for (int e = 0; e < 8; e++) { c0[e] = h0[t][e]; c1[e] = h1[t][e] + tot0s[e]; }
    for (int k = 0; k < 16; k++) {
        int s = base + k;
        {
            int e = g_topi[2 * s + 0];
            int pos = c0[e]++;
            int keep = (pos < CDIM);
            int posc = keep ? pos : (CDIM - 1);
            g_dexp[2 * s + 0] = e;
            g_dpos[2 * s + 0] = posc;
            g_dg  [2 * s + 0] = keep ? g_gate[2 * s + 0] : 0.f;
            if (keep) g_src[e * CDIM + posc] = s;
        }
        {
            int e = g_topi[2 * s + 1];
            int pos = c1[e]++;
            int keep = (pos < CDIM);
            int posc = keep ? pos : (CDIM - 1);
            g_dexp[2 * s + 1] = e;
            g_dpos[2 * s + 1] = posc;
            g_dg  [2 * s + 1] = keep ? g_gate[2 * s + 1] : 0.f;
            if (keep) g_src[e * CDIM + posc] = s;
        }
    }
}

// ---------------- 3. fp16 mma.sync fused GEMM -----------------------------
// CTA tile 128(C) x 128(H), BK=64 per pipeline step, NS=3, 256 thr,
// 2 CTAs/SM. A rows padded to 144B (9x16B, r*9 mod 8 = r mod 8 ->
// ldmatrix conflict-free); B k-rows 256B, XOR-8 16B-unit swizzle.
#define NS   3
#define AH   0
#define BH   18432
#define STG  34816
#define NIT  16
#define GEMM_SMEM (NS * STG)

__global__ __launch_bounds__(256, 2)
void moe_gemm_fp16(const float* __restrict__ b1) {
    extern __shared__ char smem[];
    __shared__ int   rowsrc[128];
    __shared__ float b1s[128];
    __shared__ float w2ss[128];

    const int tid  = threadIdx.x;
    const int lane = tid & 31;
    const int wid  = tid >> 5;
    const int e  = blockIdx.z;
    const int cb = blockIdx.y * 128;
    const int nb = blockIdx.x * 128;

    if (tid < 128) {
        rowsrc[tid] = g_src[e * CDIM + cb + tid];
        b1s[tid]  = b1[e * HDIM + nb + tid];
        w2ss[tid] = g_w2s[e * HDIM + nb + tid];
    }
    __syncthreads();
    const uint32_t sb = smem_u32(smem);

    // ---- cp.async assignments (per 64-k stage) ----
    // A: thread covers row ar = tid>>1, units ub..ub+3 (ub = (tid&1)*4)
    const int ar = tid >> 1, ub = (tid & 1) * 4;
    const int s0 = rowsrc[ar];
    const uint32_t szA = (s0 >= 0) ? 16u : 0u;
    const char* gx = (const char*)g_xh
                   + ((size_t)(s0 < 0 ? 0 : s0) * MDIM + ub * 8) * 2;
    const uint32_t aoff = (uint32_t)(ar * 144 + ub * 16);
    // B: thread covers k-row br = tid>>2, units (tid&3)*4 + v
    const int br = tid >> 2, bg = tid & 3;
    uint32_t sBoff[4], gBcol[4];
#pragma unroll
    for (int v = 0; v < 4; v++) {
        int u = bg * 4 + v;
        sBoff[v] = (uint32_t)(br * 256 + ((u ^ (br & 7)) << 4));
        gBcol[v] = (uint32_t)((nb + u * 8) * 2);
    }
    const char* gbrow = (const char*)g_w1h + ((size_t)e * MDIM + br) * (HDIM * 2);

#define LOAD_STAGE(i) do {                                                    \
    const int _k0 = (i) * 64;                                                 \
    const uint32_t _st = sb + ((i) % NS) * STG;                               \
    _Pragma("unroll")                                                         \
    for (int _u = 0; _u < 4; _u++)                                            \
        CP_ASYNC_Z(_st + AH + aoff + _u * 16, gx + (_k0 + _u * 8) * 2, szA);  \
    const char* _gb = gbrow + (size_t)_k0 * (HDIM * 2);                       \
    _Pragma("unroll")                                                         \
    for (int _v = 0; _v < 4; _v++)                                            \
        CP_ASYNC(_st + BH + sBoff[_v], _gb + gBcol[_v]);                      \
    CP_COMMIT();                                                              \
} while (0)

    // ---- mma thread geometry: 8 warps = 2 (m) x 4 (n), warp tile 64x32 ----
    const int m0 = (wid & 1) * 64;
    const int n0 = (wid >> 1) * 32;
    const uint32_t a_l = (uint32_t)((m0 + (lane & 15)) * 144
                                    + ((lane >> 4) & 1) * 16);
    const int krow = lane & 15;
    const int un0  = (n0 >> 3) + (lane >> 4);
    const uint32_t bcol0 = (uint32_t)(((un0 + 0) ^ (krow & 7)) << 4);
    const uint32_t bcol1 = (uint32_t)(((un0 + 2) ^ (krow & 7)) << 4);

    float acc[4][4][4];
#pragma unroll
    for (int mi = 0; mi < 4; mi++)
#pragma unroll
        for (int nj = 0; nj < 4; nj++)
#pragma unroll
            for (int q = 0; q < 4; q++) acc[mi][nj][q] = 0.f;

    LOAD_STAGE(0);
    LOAD_STAGE(1);

    for (int i = 0; i < NIT; i++) {
        CP_WAIT(1);
        __syncthreads();
        if (i + 2 < NIT) LOAD_STAGE(i + 2); else CP_COMMIT();

        const uint32_t st = sb + (i % NS) * STG;
        const uint32_t ab = st + AH + a_l;
        const uint32_t bbase = st + BH;
#pragma unroll
        for (int kk = 0; kk < 4; kk++) {
            uint32_t a[4][4], b[2][4];
#pragma unroll
            for (int mi = 0; mi < 4; mi++)
                LDSM4(a[mi], ab + mi * (16 * 144) + kk * 32);
            {
                uint32_t bk = bbase + (uint32_t)((krow + kk * 16) * 256);
                LDSM4T(b[0], bk + bcol0);
                LDSM4T(b[1], bk + bcol1);
            }
#pragma unroll
            for (int mi = 0; mi < 4; mi++)
#pragma unroll
                for (int nj = 0; nj < 2; nj++) {
                    MMA_F16(acc[mi][nj * 2 + 0], a[mi], b[nj][0], b[nj][1]);
                    MMA_F16(acc[mi][nj * 2 + 1], a[mi], b[nj][2], b[nj][3]);
                }
        }
    }

    // ---- fused epilogue: relu(+b1) . w2s, reduce, atomicAdd into g_z ----
    const int rr = lane >> 2;
    const int cc = (lane & 3) * 2;
#pragma unroll
    for (int mi = 0; mi < 4; mi++) {
        float pl = 0.f, ph = 0.f;
#pragma unroll
        for (int nj = 0; nj < 4; nj++) {
            int col = n0 + nj * 8 + cc;
            float w0 = w2ss[col], w1v = w2ss[col + 1];
            float bb0 = b1s[col], bb1 = b1s[col + 1];
            pl += fmaxf(acc[mi][nj][0] + bb0, 0.f) * w0
                + fmaxf(acc[mi][nj][1] + bb1, 0.f) * w1v;
            ph += fmaxf(acc[mi][nj][2] + bb0, 0.f) * w0
                + fmaxf(acc[mi][nj][3] + bb1, 0.f) * w1v;
        }
        pl += __shfl_xor_sync(0xffffffffu, pl, 1);
        pl += __shfl_xor_sync(0xffffffffu, pl, 2);
        ph += __shfl_xor_sync(0xffffffffu, ph, 1);
        ph += __shfl_xor_sync(0xffffffffu, ph, 2);
        if ((lane & 3) == 0) {
            int row = cb + m0 + mi * 16 + rr;
            atomicAdd(&g_z[e * CDIM + row], pl);
            atomicAdd(&g_z[e * CDIM + row + 8], ph);
        }
    }
#undef LOAD_STAGE
}

// ---------------- 4. fused combine + log_softmax --------------------------
__global__ void combine_lsm_kernel(float* __restrict__ out) {
    __shared__ float buf[2048];
    __shared__ float sred[1024];
    int b = blockIdx.x, t = threadIdx.x;
    for (int i = t; i < 2048; i += 1024) {
        int s = b * 2048 + i;
        float v = 0.f;
#pragma unroll
        for (int j = 0; j < 2; j++) {
            int   e = g_dexp[2 * s + j];
            int   p = g_dpos[2 * s + j];
            float g = g_dg  [2 * s + j];
            v += g * (g_z[e * CDIM + p] + g_b2s[e]);
        }
        buf[i] = v;
    }
    __syncthreads();
    float mx = fmaxf(buf[t], buf[t + 1024]);
    sred[t] = mx; __syncthreads();
    for (int o = 512; o > 0; o >>= 1) {
        if (t < o) sred[t] = fmaxf(sred[t], sred[t + o]);
        __syncthreads();
    }
    mx = sred[0]; __syncthreads();
    float sm = expf(buf[t] - mx) + expf(buf[t + 1024] - mx);
    sred[t] = sm; __syncthreads();
    for (int o = 512; o > 0; o >>= 1) {
        if (t < o) sred[t] += sred[t + o];
        __syncthreads();
    }
    float lse = mx + logf(sred[0]);
    for (int i = t; i < 2048; i += 1024)
        out[(size_t)b * 2048 + i] = buf[i] - lse;
}

// ---------------- launch ---------------------------------------------------
extern "C" void kernel_launch(void* const* d_in, const int* in_sizes, int n_in,
                              void* d_out, int out_size) {
    const float* x  = (const float*)d_in[0];
    const float* wg = (const float*)d_in[1];
    const float* w1 = (const float*)d_in[2];
    const float* b1 = (const float*)d_in[3];
    const float* w2 = (const float*)d_in[4];
    const float* b2 = (const float*)d_in[5];
    float* out = (float*)d_out;

    fused_prep_kernel<<<NW4B + 2049 + RTRB, 256>>>(x, wg, w1, w2, b2);
    scan_kernel<<<1, 512>>>();

    cudaFuncSetAttribute(moe_gemm_fp16,
                         cudaFuncAttributeMaxDynamicSharedMemorySize, GEMM_SMEM);
    moe_gemm_fp16<<<dim3(HDIM / 128, CDIM / 128, EDIM), 256, GEMM_SMEM>>>(b1);

    combine_lsm_kernel<<<4, 1024>>>(out);
}

// round 14
// speedup vs baseline: 1.2119x; 1.2119x over previous
#include <cuda_runtime.h>
#include <cuda_fp16.h>
#include <math.h>
#include <stdint.h>

#define S_TOK 8192
#define MDIM  1024
#define HDIM  2048
#define EDIM  8
#define CDIM  2048

// ---------------- scratch (device globals; no allocation) ----------------
__device__ int   g_topi[S_TOK * 2];
__device__ float g_gate[S_TOK * 2];
__device__ int   g_dexp[S_TOK * 2];
__device__ int   g_dpos[S_TOK * 2];
__device__ float g_dg  [S_TOK * 2];
__device__ int   g_src [EDIM * CDIM];
__device__ float g_z   [EDIM * CDIM];
__device__ float g_w2s [EDIM * HDIM];
__device__ float g_b2s [EDIM];
// fp16 copies for MMA
__device__ __half g_xh [(size_t)S_TOK * MDIM];
__device__ __half g_w1h[(size_t)EDIM * MDIM * HDIM];

// ---- side stream + events, created at static-init (host objects) --------
struct SideInit {
    cudaStream_t s;
    cudaEvent_t e1, e2;
    SideInit() {
        cudaStreamCreateWithFlags(&s, cudaStreamNonBlocking);
        cudaEventCreateWithFlags(&e1, cudaEventDisableTiming);
        cudaEventCreateWithFlags(&e2, cudaEventDisableTiming);
    }
};
static SideInit g_sideinit;

// ---------------- helpers -------------------------------------------------
__device__ __forceinline__ uint32_t smem_u32(const void* p) {
    uint32_t a;
    asm("{ .reg .u64 t; cvta.to.shared.u64 t, %1; cvt.u32.u64 %0, t; }"
        : "=r"(a) : "l"(p));
    return a;
}
#define CP_ASYNC(saddr, gptr) \
    asm volatile("cp.async.cg.shared.global [%0], [%1], 16;" \
        :: "r"(saddr), "l"(gptr) : "memory")
#define CP_ASYNC_Z(saddr, gptr, srcsz) \
    asm volatile("cp.async.cg.shared.global [%0], [%1], 16, %2;" \
        :: "r"(saddr), "l"(gptr), "r"(srcsz) : "memory")
#define CP_COMMIT() asm volatile("cp.async.commit_group;" ::: "memory")
#define CP_WAIT(n)  asm volatile("cp.async.wait_group %0;" :: "n"(n) : "memory")

#define LDSM4(r, addr) \
    asm volatile("ldmatrix.sync.aligned.m8n8.x4.shared.b16 {%0,%1,%2,%3}, [%4];" \
        : "=r"((r)[0]), "=r"((r)[1]), "=r"((r)[2]), "=r"((r)[3]) : "r"(addr))
#define LDSM4T(r, addr) \
    asm volatile("ldmatrix.sync.aligned.m8n8.x4.trans.shared.b16 {%0,%1,%2,%3}, [%4];" \
        : "=r"((r)[0]), "=r"((r)[1]), "=r"((r)[2]), "=r"((r)[3]) : "r"(addr))
#define MMA_F16(d, a, b0, b1) \
    asm volatile("mma.sync.aligned.m16n8k16.row.col.f32.f16.f16.f32 " \
        "{%0,%1,%2,%3}, {%4,%5,%6,%7}, {%8,%9}, {%0,%1,%2,%3};" \
        : "+f"((d)[0]), "+f"((d)[1]), "+f"((d)[2]), "+f"((d)[3]) \
        : "r"((a)[0]), "r"((a)[1]), "r"((a)[2]), "r"((a)[3]), "r"(b0), "r"(b1))

// ---------------- 1. router (also emits fp16 x) ---------------------------
__global__ void routing_kernel(const float* __restrict__ x,
                               const float* __restrict__ wg) {
    int warp = (blockIdx.x * blockDim.x + threadIdx.x) >> 5;
    int lane = threadIdx.x & 31;
    if (warp >= S_TOK) return;
    const float* xr = x + (size_t)warp * MDIM;
    __half* xh = g_xh + (size_t)warp * MDIM;
    float acc[8];
#pragma unroll
    for (int e = 0; e < 8; e++) acc[e] = 0.f;
    for (int m = lane; m < MDIM; m += 32) {
        float xv = xr[m];
        xh[m] = __float2half_rn(xv);
        const float* wr = wg + m * 8;
        float4 w0 = *(const float4*)(wr);
        float4 w1 = *(const float4*)(wr + 4);
        acc[0] += xv * w0.x; acc[1] += xv * w0.y;
        acc[2] += xv * w0.z; acc[3] += xv * w0.w;
        acc[4] += xv * w1.x; acc[5] += xv * w1.y;
        acc[6] += xv * w1.z; acc[7] += xv * w1.w;
    }
#pragma unroll
    for (int off = 16; off > 0; off >>= 1)
#pragma unroll
        for (int e = 0; e < 8; e++)
            acc[e] += __shfl_down_sync(0xffffffffu, acc[e], off);
    if (lane == 0) {
        float mx = acc[0];
#pragma unroll
        for (int e = 1; e < 8; e++) mx = fmaxf(mx, acc[e]);
        float sc[8], s = 0.f;
#pragma unroll
        for (int e = 0; e < 8; e++) { sc[e] = expf(acc[e] - mx); s += sc[e]; }
        float inv = 1.f / s;
#pragma unroll
        for (int e = 0; e < 8; e++) sc[e] *= inv;
        int i0 = 0;
#pragma unroll
        for (int e = 1; e < 8; e++) if (sc[e] > sc[i0]) i0 = e;
        int i1 = -1;
#pragma unroll
        for (int e = 0; e < 8; e++) {
            if (e == i0) continue;
            if (i1 < 0 || sc[e] > sc[i1]) i1 = e;
        }
        float v0 = sc[i0], v1 = sc[i1];
        float den = 1.f / (v0 + v1 + 1e-9f);
        g_topi[warp * 2 + 0] = i0;
        g_topi[warp * 2 + 1] = i1;
        g_gate[warp * 2 + 0] = v0 * den;
        g_gate[warp * 2 + 1] = v1 * den;
    }
}

// ---------------- 2. ordered scan (512 thr, warp-parallel bin scans) ------
__global__ void scan_kernel() {
    __shared__ int h0[512][9];
    __shared__ int h1[512][9];
    __shared__ int tot0s[8];
    int t = threadIdx.x;
    for (int i = t; i < EDIM * CDIM; i += 512) { g_src[i] = -1; g_z[i] = 0.f; }

    int c0[8], c1[8];
#pragma unroll
    for (int e = 0; e < 8; e++) { c0[e] = 0; c1[e] = 0; }
    int base = t * 16;
    for (int k = 0; k < 16; k++) {
        int s = base + k;
        c0[g_topi[2 * s + 0]]++;
        c1[g_topi[2 * s + 1]]++;
    }
#pragma unroll
    for (int e = 0; e < 8; e++) { h0[t][e] = c0[e]; h1[t][e] = c1[e]; }
    __syncthreads();

    int wid = t >> 5, lane = t & 31;
    if (wid < 16) {
        int e = wid & 7, which = wid >> 3;
        int vals[16], run = 0;
#pragma unroll
        for (int j = 0; j < 16; j++) {
            int v = which ? h1[lane * 16 + j][e] : h0[lane * 16 + j][e];
            vals[j] = run; run += v;
        }
        int tot = run;
#pragma unroll
        for (int off = 1; off < 32; off <<= 1) {
            int n = __shfl_up_sync(0xffffffffu, tot, off);
            if (lane >= off) tot += n;
        }
        int excl = tot - run;
#pragma unroll
        for (int j = 0; j < 16; j++) {
            if (which) h1[lane * 16 + j][e] = vals[j] + excl;
            else       h0[lane * 16 + j][e] = vals[j] + excl;
        }
        if (lane == 31 && which == 0) tot0s[e] = tot;
    }
    __syncthreads();

#pragma unroll
    for (int e = 0; e < 8; e++) { c0[e] = h0[t][e]; c1[e] = h1[t][e] + tot0s[e]; }
    for (int k = 0; k < 16; k++) {
        int s = base + k;
        {
            int e = g_topi[2 * s + 0];
            int pos = c0[e]++;
            int keep = (pos < CDIM);
            int posc = keep ? pos : (CDIM - 1);
            g_dexp[2 * s + 0] = e;
            g_dpos[2 * s + 0] = posc;
            g_dg  [2 * s + 0] = keep ? g_gate[2 * s + 0] : 0.f;
            if (keep) g_src[e * CDIM + posc] = s;
        }
        {
            int e = g_topi[2 * s + 1];
            int pos = c1[e]++;
            int keep = (pos < CDIM);
            int posc = keep ? pos : (CDIM - 1);
            g_dexp[2 * s + 1] = e;
            g_dpos[2 * s + 1] = posc;
            g_dg  [2 * s + 1] = keep ? g_gate[2 * s + 1] : 0.f;
            if (keep) g_src[e * CDIM + posc] = s;
        }
    }
}

// ---------------- 3. merged prep: w1 -> fp16, w2s/b2s reductions ----------
#define NW4  (EDIM * MDIM * HDIM / 4)
#define NW4B (NW4 / 256)
__global__ void prep_kernel(const float* __restrict__ w1,
                            const float* __restrict__ w2,
                            const float* __restrict__ b2) {
    int b = blockIdx.x;
    if (b < NW4B) {
        int i = b * 256 + threadIdx.x;
        float4 v = ((const float4*)w1)[i];
        __half2 h01 = __floats2half2_rn(v.x, v.y);
        __half2 h23 = __floats2half2_rn(v.z, v.w);
        ((uint2*)g_w1h)[i] = make_uint2(*(uint32_t*)&h01, *(uint32_t*)&h23);
        return;
    }
    int warp = (b - NW4B) * 8 + (threadIdx.x >> 5);
    int lane = threadIdx.x & 31;
    if (warp < EDIM * HDIM) {
        const float4* r = (const float4*)(w2 + (size_t)warp * MDIM);
        float s = 0.f;
        for (int m = lane; m < MDIM / 4; m += 32) {
            float4 v = r[m];
            s += v.x + v.y + v.z + v.w;
        }
#pragma unroll
        for (int off = 16; off > 0; off >>= 1) s += __shfl_down_sync(0xffffffffu, s, off);
        if (lane == 0) g_w2s[warp] = s;
    } else if (warp < EDIM * HDIM + EDIM) {
        int e = warp - EDIM * HDIM;
        const float4* r = (const float4*)(b2 + (size_t)e * MDIM);
        float s = 0.f;
        for (int m = lane; m < MDIM / 4; m += 32) {
            float4 v = r[m];
            s += v.x + v.y + v.z + v.w;
        }
#pragma unroll
        for (int off = 16; off > 0; off >>= 1) s += __shfl_down_sync(0xffffffffu, s, off);
        if (lane == 0) g_b2s[e] = s;
    }
}

// ---------------- 4. fp16 mma.sync fused GEMM (R10 geometry, NS=5) --------
// CTA tile 128(C) x 128(H), BK=32, 5-stage cp.async pipeline, 256 thr,
// 2 CTAs/SM. A rows padded to 80B; B k-rows 256B, XOR-8 16B-unit swizzle.
#define NS   5
#define AH   0
#define BH   10240
#define STG  18432
#define GEMM_SMEM (NS * STG)

__global__ __launch_bounds__(256, 2)
void moe_gemm_fp16(const float* __restrict__ b1) {
    extern __shared__ char smem[];
    __shared__ int   rowsrc[128];
    __shared__ float b1s[128];
    __shared__ float w2ss[128];

    const int tid  = threadIdx.x;
    const int lane = tid & 31;
    const int wid  = tid >> 5;
    const int e  = blockIdx.z;
    const int cb = blockIdx.y * 128;
    const int nb = blockIdx.x * 128;

    if (tid < 128) {
        rowsrc[tid] = g_src[e * CDIM + cb + tid];
        b1s[tid]  = b1[e * HDIM + nb + tid];
        w2ss[tid] = g_w2s[e * HDIM + nb + tid];
    }
    __syncthreads();
    const uint32_t sb = smem_u32(smem);

    // ---- cp.async assignments ----
    const int ar = tid >> 2, au = tid & 3;
    const int s0 = rowsrc[ar], s1 = rowsrc[ar + 64];
    const uint32_t sz0 = (s0 >= 0) ? 16u : 0u;
    const uint32_t sz1 = (s1 >= 0) ? 16u : 0u;
    const char* gx0 = (const char*)g_xh + ((size_t)(s0 < 0 ? 0 : s0) * MDIM + au * 8) * 2;
    const char* gx1 = (const char*)g_xh + ((size_t)(s1 < 0 ? 0 : s1) * MDIM + au * 8) * 2;
    const uint32_t aoff0 = (uint32_t)(ar * 80 + au * 16);
    const uint32_t aoff1 = (uint32_t)((ar + 64) * 80 + au * 16);
    const int br = tid >> 4, bu = tid & 15;
    const char* gb = (const char*)g_w1h + (((size_t)e * MDIM) * HDIM + nb + bu * 8) * 2;
    const uint32_t sB0 = (uint32_t)(br * 256 + ((bu ^ (br & 7)) << 4));
    const uint32_t sB1 = sB0 + 16 * 256;

#define LOAD_STAGE(i) do {                                                    \
    const int _k0 = (i) * 32;                                                 \
    const uint32_t _st = sb + ((i) % NS) * STG;                               \
    CP_ASYNC_Z(_st + AH + aoff0, gx0 + _k0 * 2, sz0);                         \
    CP_ASYNC_Z(_st + AH + aoff1, gx1 + _k0 * 2, sz1);                         \
    const size_t _g = (size_t)(_k0 + br) * (HDIM * 2);                        \
    CP_ASYNC(_st + BH + sB0, gb + _g);                                        \
    CP_ASYNC(_st + BH + sB1, gb + _g + (size_t)16 * HDIM * 2);                \
    CP_COMMIT();                                                              \
} while (0)

    // ---- mma thread geometry: 8 warps = 2 (m) x 4 (n), warp tile 64x32 ----
    const int m0 = (wid & 1) * 64;
    const int n0 = (wid >> 1) * 32;
    const uint32_t a_l = (uint32_t)((m0 + (lane & 15)) * 80 + ((lane >> 4) & 1) * 16);
    const int krow = lane & 15;
    const int un0  = (n0 >> 3) + (lane >> 4);
    const uint32_t b_row = (uint32_t)(krow * 256);
    const uint32_t bcol0 = (uint32_t)(((un0 + 0) ^ (krow & 7)) << 4);
    const uint32_t bcol1 = (uint32_t)(((un0 + 2) ^ (krow & 7)) << 4);

    float acc[4][4][4];
#pragma unroll
    for (int mi = 0; mi < 4; mi++)
#pragma unroll
        for (int nj = 0; nj < 4; nj++)
#pragma unroll
            for (int q = 0; q < 4; q++) acc[mi][nj][q] = 0.f;

    LOAD_STAGE(0);
    LOAD_STAGE(1);
    LOAD_STAGE(2);
    LOAD_STAGE(3);

    for (int i = 0; i < 32; i++) {
        CP_WAIT(3);
        __syncthreads();
        if (i + 4 < 32) LOAD_STAGE(i + 4); else CP_COMMIT();

        const uint32_t st = sb + (i % NS) * STG;
        const uint32_t ab = st + AH + a_l;
        const uint32_t bb = st + BH + b_row;
#pragma unroll
        for (int kk = 0; kk < 2; kk++) {
            uint32_t a[4][4], b[2][4];
#pragma unroll
            for (int mi = 0; mi < 4; mi++)
                LDSM4(a[mi], ab + mi * (16 * 80) + kk * 32);
            {
                uint32_t kb = (uint32_t)(kk * 16 * 256);
                LDSM4T(b[0], bb + kb + bcol0);
                LDSM4T(b[1], bb + kb + bcol1);
            }
#pragma unroll
            for (int mi = 0; mi < 4; mi++)
#pragma unroll
                for (int nj = 0; nj < 2; nj++) {
                    MMA_F16(acc[mi][nj * 2 + 0], a[mi], b[nj][0], b[nj][1]);
                    MMA_F16(acc[mi][nj * 2 + 1], a[mi], b[nj][2], b[nj][3]);
                }
        }
    }

    // ---- fused epilogue: relu(+b1) . w2s, reduce, atomicAdd into g_z ----
    const int rr = lane >> 2;
    const int cc = (lane & 3) * 2;
#pragma unroll
    for (int mi = 0; mi < 4; mi++) {
        float pl = 0.f, ph = 0.f;
#pragma unroll
        for (int nj = 0; nj < 4; nj++) {
            int col = n0 + nj * 8 + cc;
            float w0 = w2ss[col], w1v = w2ss[col + 1];
            float bb0 = b1s[col], bb1 = b1s[col + 1];
            pl += fmaxf(acc[mi][nj][0] + bb0, 0.f) * w0
                + fmaxf(acc[mi][nj][1] + bb1, 0.f) * w1v;
            ph += fmaxf(acc[mi][nj][2] + bb0, 0.f) * w0
                + fmaxf(acc[mi][nj][3] + bb1, 0.f) * w1v;
        }
        pl += __shfl_xor_sync(0xffffffffu, pl, 1);
        pl += __shfl_xor_sync(0xffffffffu, pl, 2);
        ph += __shfl_xor_sync(0xffffffffu, ph, 1);
        ph += __shfl_xor_sync(0xffffffffu, ph, 2);
        if ((lane & 3) == 0) {
            int row = cb + m0 + mi * 16 + rr;
            atomicAdd(&g_z[e * CDIM + row], pl);
            atomicAdd(&g_z[e * CDIM + row + 8], ph);
        }
    }
#undef LOAD_STAGE
}

// ---------------- 5. fused combine + log_softmax --------------------------
__global__ void combine_lsm_kernel(float* __restrict__ out) {
    __shared__ float buf[2048];
    __shared__ float sred[512];
    int b = blockIdx.x, t = threadIdx.x;
    for (int i = t; i < 2048; i += 512) {
        int s = b * 2048 + i;
        float v = 0.f;
#pragma unroll
        for (int j = 0; j < 2; j++) {
            int   e = g_dexp[2 * s + j];
            int   p = g_dpos[2 * s + j];
            float g = g_dg  [2 * s + j];
            v += g * (g_z[e * CDIM + p] + g_b2s[e]);
        }
        buf[i] = v;
    }
    __syncthreads();
    float mx = -1e30f;
    for (int i = t; i < 2048; i += 512) mx = fmaxf(mx, buf[i]);
    sred[t] = mx; __syncthreads();
    for (int o = 256; o > 0; o >>= 1) {
        if (t < o) sred[t] = fmaxf(sred[t], sred[t + o]);
        __syncthreads();
    }
    mx = sred[0]; __syncthreads();
    float sm = 0.f;
    for (int i = t; i < 2048; i += 512) sm += expf(buf[i] - mx);
    sred[t] = sm; __syncthreads();
    for (int o = 256; o > 0; o >>= 1) {
        if (t < o) sred[t] += sred[t + o];
        __syncthreads();
    }
    float lse = mx + logf(sred[0]);
    for (int i = t; i < 2048; i += 512)
        out[(size_t)b * 2048 + i] = buf[i] - lse;
}

// ---------------- launch ---------------------------------------------------
extern "C" void kernel_launch(void* const* d_in, const int* in_sizes, int n_in,
                              void* d_out, int out_size) {
    const float* x  = (const float*)d_in[0];
    const float* wg = (const float*)d_in[1];
    const float* w1 = (const float*)d_in[2];
    const float* b1 = (const float*)d_in[3];
    const float* w2 = (const float*)d_in[4];
    const float* b2 = (const float*)d_in[5];
    float* out = (float*)d_out;

    // fork: prep (w1 conversion + w2s/b2s) runs on the side stream,
    // concurrent with routing + scan on the main (capture) stream.
    cudaEventRecord(g_sideinit.e1, (cudaStream_t)0);
    cudaStreamWaitEvent(g_sideinit.s, g_sideinit.e1, 0);
    prep_kernel<<<NW4B + 2049, 256, 0, g_sideinit.s>>>(w1, w2, b2);
    cudaEventRecord(g_sideinit.e2, g_sideinit.s);

    routing_kernel<<<S_TOK / 8, 256>>>(x, wg);
    scan_kernel<<<1, 512>>>();

    // join: GEMM needs both branches
    cudaStreamWaitEvent((cudaStream_t)0, g_sideinit.e2, 0);

    cudaFuncSetAttribute(moe_gemm_fp16,
                         cudaFuncAttributeMaxDynamicSharedMemorySize, GEMM_SMEM);
    moe_gemm_fp16<<<dim3(HDIM / 128, CDIM / 128, EDIM), 256, GEMM_SMEM>>>(b1);

    combine_lsm_kernel<<<4, 512>>>(out);
}

// round 15
// speedup vs baseline: 1.2517x; 1.0328x over previous
#include <cuda_runtime.h>
#include <cuda_fp16.h>
#include <math.h>
#include <stdint.h>

#define S_TOK 8192
#define MDIM  1024
#define HDIM  2048
#define EDIM  8
#define CDIM  2048

// ---------------- scratch (device globals; no allocation) ----------------
__device__ int   g_topi[S_TOK * 2];
__device__ float g_gate[S_TOK * 2];
__device__ int   g_dexp[S_TOK * 2];
__device__ int   g_dpos[S_TOK * 2];
__device__ float g_dg  [S_TOK * 2];
__device__ int   g_src [EDIM * CDIM];
__device__ float g_z   [EDIM * CDIM];
__device__ float g_w2s [EDIM * HDIM];
__device__ float g_b2s [EDIM];
// fp16 copies for MMA
__device__ __half g_xh [(size_t)S_TOK * MDIM];
__device__ __half g_w1h[(size_t)EDIM * MDIM * HDIM];

// ---- side stream + events, created at static-init (host objects) --------
struct SideInit {
    cudaStream_t s;
    cudaEvent_t e1, e2;
    SideInit() {
        cudaStreamCreateWithFlags(&s, cudaStreamNonBlocking);
        cudaEventCreateWithFlags(&e1, cudaEventDisableTiming);
        cudaEventCreateWithFlags(&e2, cudaEventDisableTiming);
    }
};
static SideInit g_sideinit;

// ---------------- helpers -------------------------------------------------
__device__ __forceinline__ uint32_t smem_u32(const void* p) {
    uint32_t a;
    asm("{ .reg .u64 t; cvta.to.shared.u64 t, %1; cvt.u32.u64 %0, t; }"
        : "=r"(a) : "l"(p));
    return a;
}
#define CP_ASYNC(saddr, gptr) \
    asm volatile("cp.async.cg.shared.global [%0], [%1], 16;" \
        :: "r"(saddr), "l"(gptr) : "memory")
#define CP_ASYNC_Z(saddr, gptr, srcsz) \
    asm volatile("cp.async.cg.shared.global [%0], [%1], 16, %2;" \
        :: "r"(saddr), "l"(gptr), "r"(srcsz) : "memory")
#define CP_COMMIT() asm volatile("cp.async.commit_group;" ::: "memory")
#define CP_WAIT(n)  asm volatile("cp.async.wait_group %0;" :: "n"(n) : "memory")

#define LDSM4(r, addr) \
    asm volatile("ldmatrix.sync.aligned.m8n8.x4.shared.b16 {%0,%1,%2,%3}, [%4];" \
        : "=r"((r)[0]), "=r"((r)[1]), "=r"((r)[2]), "=r"((r)[3]) : "r"(addr))
#define LDSM4T(r, addr) \
    asm volatile("ldmatrix.sync.aligned.m8n8.x4.trans.shared.b16 {%0,%1,%2,%3}, [%4];" \
        : "=r"((r)[0]), "=r"((r)[1]), "=r"((r)[2]), "=r"((r)[3]) : "r"(addr))
#define MMA_F16(d, a, b0, b1) \
    asm volatile("mma.sync.aligned.m16n8k16.row.col.f32.f16.f16.f32 " \
        "{%0,%1,%2,%3}, {%4,%5,%6,%7}, {%8,%9}, {%0,%1,%2,%3};" \
        : "+f"((d)[0]), "+f"((d)[1]), "+f"((d)[2]), "+f"((d)[3]) \
        : "r"((a)[0]), "r"((a)[1]), "r"((a)[2]), "r"((a)[3]), "r"(b0), "r"(b1))

// ---------------- 1. router (also emits fp16 x) ---------------------------
__global__ void routing_kernel(const float* __restrict__ x,
                               const float* __restrict__ wg) {
    int warp = (blockIdx.x * blockDim.x + threadIdx.x) >> 5;
    int lane = threadIdx.x & 31;
    if (warp >= S_TOK) return;
    const float* xr = x + (size_t)warp * MDIM;
    __half* xh = g_xh + (size_t)warp * MDIM;
    float acc[8];
#pragma unroll
    for (int e = 0; e < 8; e++) acc[e] = 0.f;
    for (int m = lane; m < MDIM; m += 32) {
        float xv = xr[m];
        xh[m] = __float2half_rn(xv);
        const float* wr = wg + m * 8;
        float4 w0 = *(const float4*)(wr);
        float4 w1 = *(const float4*)(wr + 4);
        acc[0] += xv * w0.x; acc[1] += xv * w0.y;
        acc[2] += xv * w0.z; acc[3] += xv * w0.w;
        acc[4] += xv * w1.x; acc[5] += xv * w1.y;
        acc[6] += xv * w1.z; acc[7] += xv * w1.w;
    }
#pragma unroll
    for (int off = 16; off > 0; off >>= 1)
#pragma unroll
        for (int e = 0; e < 8; e++)
            acc[e] += __shfl_down_sync(0xffffffffu, acc[e], off);
    if (lane == 0) {
        float mx = acc[0];
#pragma unroll
        for (int e = 1; e < 8; e++) mx = fmaxf(mx, acc[e]);
        float sc[8], s = 0.f;
#pragma unroll
        for (int e = 0; e < 8; e++) { sc[e] = expf(acc[e] - mx); s += sc[e]; }
        float inv = 1.f / s;
#pragma unroll
        for (int e = 0; e < 8; e++) sc[e] *= inv;
        int i0 = 0;
#pragma unroll
        for (int e = 1; e < 8; e++) if (sc[e] > sc[i0]) i0 = e;
        int i1 = -1;
#pragma unroll
        for (int e = 0; e < 8; e++) {
            if (e == i0) continue;
            if (i1 < 0 || sc[e] > sc[i1]) i1 = e;
        }
        float v0 = sc[i0], v1 = sc[i1];
        float den = 1.f / (v0 + v1 + 1e-9f);
        g_topi[warp * 2 + 0] = i0;
        g_topi[warp * 2 + 1] = i1;
        g_gate[warp * 2 + 0] = v0 * den;
        g_gate[warp * 2 + 1] = v1 * den;
    }
}

// ---------------- 2. ordered scan (512 thr, warp-parallel bin scans) ------
__global__ void scan_kernel() {
    __shared__ int h0[512][9];
    __shared__ int h1[512][9];
    __shared__ int tot0s[8];
    int t = threadIdx.x;
    for (int i = t; i < EDIM * CDIM; i += 512) { g_src[i] = -1; g_z[i] = 0.f; }

    int c0[8], c1[8];
#pragma unroll
    for (int e = 0; e < 8; e++) { c0[e] = 0; c1[e] = 0; }
    int base = t * 16;
    for (int k = 0; k < 16; k++) {
        int s = base + k;
        c0[g_topi[2 * s + 0]]++;
        c1[g_topi[2 * s + 1]]++;
    }
#pragma unroll
    for (int e = 0; e < 8; e++) { h0[t][e] = c0[e]; h1[t][e] = c1[e]; }
    __syncthreads();

    int wid = t >> 5, lane = t & 31;
    if (wid < 16) {
        int e = wid & 7, which = wid >> 3;
        int vals[16], run = 0;
#pragma unroll
        for (int j = 0; j < 16; j++) {
            int v = which ? h1[lane * 16 + j][e] : h0[lane * 16 + j][e];
            vals[j] = run; run += v;
        }
        int tot = run;
#pragma unroll
        for (int off = 1; off < 32; off <<= 1) {
            int n = __shfl_up_sync(0xffffffffu, tot, off);
            if (lane >= off) tot += n;
        }
        int excl = tot - run;
#pragma unroll
        for (int j = 0; j < 16; j++) {
            if (which) h1[lane * 16 + j][e] = vals[j] + excl;
            else       h0[lane * 16 + j][e] = vals[j] + excl;
        }
        if (lane == 31 && which == 0) tot0s[e] = tot;
    }
    __syncthreads();

#pragma unroll
    for (int e = 0; e < 8; e++) { c0[e] = h0[t][e]; c1[e] = h1[t][e] + tot0s[e]; }
    for (int k = 0; k < 16; k++) {
        int s = base + k;
        {
            int e = g_topi[2 * s + 0];
            int pos = c0[e]++;
            int keep = (pos < CDIM);
            int posc = keep ? pos : (CDIM - 1);
            g_dexp[2 * s + 0] = e;
            g_dpos[2 * s + 0] = posc;
            g_dg  [2 * s + 0] = keep ? g_gate[2 * s + 0] : 0.f;
            if (keep) g_src[e * CDIM + posc] = s;
        }
        {
            int e = g_topi[2 * s + 1];
            int pos = c1[e]++;
            int keep = (pos < CDIM);
            int posc = keep ? pos : (CDIM - 1);
            g_dexp[2 * s + 1] = e;
            g_dpos[2 * s + 1] = posc;
            g_dg  [2 * s + 1] = keep ? g_gate[2 * s + 1] : 0.f;
            if (keep) g_src[e * CDIM + posc] = s;
        }
    }
}

// ---------------- 3. merged prep: w1 -> fp16 (2x MLP), w2s/b2s ------------
#define NW4   (EDIM * MDIM * HDIM / 4)
#define NW4H  (NW4 / 2)
#define NW4B  (NW4H / 256)
__global__ void prep_kernel(const float* __restrict__ w1,
                            const float* __restrict__ w2,
                            const float* __restrict__ b2) {
    int b = blockIdx.x;
    if (b < NW4B) {
        int i = b * 256 + threadIdx.x;
        float4 v0 = ((const float4*)w1)[i];
        float4 v1 = ((const float4*)w1)[i + NW4H];
        __half2 a01 = __floats2half2_rn(v0.x, v0.y);
        __half2 a23 = __floats2half2_rn(v0.z, v0.w);
        __half2 b01 = __floats2half2_rn(v1.x, v1.y);
        __half2 b23 = __floats2half2_rn(v1.z, v1.w);
        ((uint2*)g_w1h)[i]        = make_uint2(*(uint32_t*)&a01, *(uint32_t*)&a23);
        ((uint2*)g_w1h)[i + NW4H] = make_uint2(*(uint32_t*)&b01, *(uint32_t*)&b23);
        return;
    }
    int warp = (b - NW4B) * 8 + (threadIdx.x >> 5);
    int lane = threadIdx.x & 31;
    if (warp < EDIM * HDIM) {
        const float4* r = (const float4*)(w2 + (size_t)warp * MDIM);
        float s = 0.f;
        for (int m = lane; m < MDIM / 4; m += 32) {
            float4 v = r[m];
            s += v.x + v.y + v.z + v.w;
        }
#pragma unroll
        for (int off = 16; off > 0; off >>= 1) s += __shfl_down_sync(0xffffffffu, s, off);
        if (lane == 0) g_w2s[warp] = s;
    } else if (warp < EDIM * HDIM + EDIM) {
        int e = warp - EDIM * HDIM;
        const float4* r = (const float4*)(b2 + (size_t)e * MDIM);
        float s = 0.f;
        for (int m = lane; m < MDIM / 4; m += 32) {
            float4 v = r[m];
            s += v.x + v.y + v.z + v.w;
        }
#pragma unroll
        for (int off = 16; off > 0; off >>= 1) s += __shfl_down_sync(0xffffffffu, s, off);
        if (lane == 0) g_b2s[e] = s;
    }
}

// ---------------- 4. fp16 mma.sync fused GEMM -----------------------------
// CTA tile 128(C) x 128(H), BK=32, NS=6, CP_WAIT(2), barrier every 2 iters
// (distance-2 overwrite guard), 256 thr, 2 CTAs/SM.
// A rows padded to 80B; B k-rows 256B, XOR-8 16B-unit swizzle.
#define NS   6
#define AH   0
#define BH   10240
#define STG  18432
#define GEMM_SMEM (NS * STG)

__global__ __launch_bounds__(256, 2)
void moe_gemm_fp16(const float* __restrict__ b1) {
    extern __shared__ char smem[];
    __shared__ int   rowsrc[128];
    __shared__ float b1s[128];
    __shared__ float w2ss[128];

    const int tid  = threadIdx.x;
    const int lane = tid & 31;
    const int wid  = tid >> 5;
    const int e  = blockIdx.z;
    const int cb = blockIdx.y * 128;
    const int nb = blockIdx.x * 128;

    if (tid < 128) {
        rowsrc[tid] = g_src[e * CDIM + cb + tid];
        b1s[tid]  = b1[e * HDIM + nb + tid];
        w2ss[tid] = g_w2s[e * HDIM + nb + tid];
    }
    __syncthreads();
    const uint32_t sb = smem_u32(smem);

    // ---- cp.async assignments ----
    const int ar = tid >> 2, au = tid & 3;
    const int s0 = rowsrc[ar], s1 = rowsrc[ar + 64];
    const uint32_t sz0 = (s0 >= 0) ? 16u : 0u;
    const uint32_t sz1 = (s1 >= 0) ? 16u : 0u;
    const char* gx0 = (const char*)g_xh + ((size_t)(s0 < 0 ? 0 : s0) * MDIM + au * 8) * 2;
    const char* gx1 = (const char*)g_xh + ((size_t)(s1 < 0 ? 0 : s1) * MDIM + au * 8) * 2;
    const uint32_t aoff0 = (uint32_t)(ar * 80 + au * 16);
    const uint32_t aoff1 = (uint32_t)((ar + 64) * 80 + au * 16);
    const int br = tid >> 4, bu = tid & 15;
    const char* gb = (const char*)g_w1h + (((size_t)e * MDIM) * HDIM + nb + bu * 8) * 2;
    const uint32_t sB0 = (uint32_t)(br * 256 + ((bu ^ (br & 7)) << 4));
    const uint32_t sB1 = sB0 + 16 * 256;

#define LOAD_STAGE(i) do {                                                    \
    const int _k0 = (i) * 32;                                                 \
    const uint32_t _st = sb + ((i) % NS) * STG;                               \
    CP_ASYNC_Z(_st + AH + aoff0, gx0 + _k0 * 2, sz0);                         \
    CP_ASYNC_Z(_st + AH + aoff1, gx1 + _k0 * 2, sz1);                         \
    const size_t _g = (size_t)(_k0 + br) * (HDIM * 2);                        \
    CP_ASYNC(_st + BH + sB0, gb + _g);                                        \
    CP_ASYNC(_st + BH + sB1, gb + _g + (size_t)16 * HDIM * 2);                \
    CP_COMMIT();                                                              \
} while (0)

    // ---- mma thread geometry: 8 warps = 2 (m) x 4 (n), warp tile 64x32 ----
    const int m0 = (wid & 1) * 64;
    const int n0 = (wid >> 1) * 32;
    const uint32_t a_l = (uint32_t)((m0 + (lane & 15)) * 80 + ((lane >> 4) & 1) * 16);
    const int krow = lane & 15;
    const int un0  = (n0 >> 3) + (lane >> 4);
    const uint32_t b_row = (uint32_t)(krow * 256);
    const uint32_t bcol0 = (uint32_t)(((un0 + 0) ^ (krow & 7)) << 4);
    const uint32_t bcol1 = (uint32_t)(((un0 + 2) ^ (krow & 7)) << 4);

    float acc[4][4][4];
#pragma unroll
    for (int mi = 0; mi < 4; mi++)
#pragma unroll
        for (int nj = 0; nj < 4; nj++)
#pragma unroll
            for (int q = 0; q < 4; q++) acc[mi][nj][q] = 0.f;

    LOAD_STAGE(0);
    LOAD_STAGE(1);
    LOAD_STAGE(2);
    LOAD_STAGE(3);

#pragma unroll 2
    for (int i = 0; i < 32; i++) {
        // wait until stage i+1 is ready (own groups <= i+1 complete)
        CP_WAIT(2);
        // barrier every 2 iters: publishes stages <= i+1 to the block and
        // bounds warp skew < 2 so LOAD_STAGE(i+4) (writes stage consumed at
        // iter i-2 with NS=6) cannot race any reader.
        if ((i & 1) == 0) __syncthreads();
        if (i + 4 < 32) LOAD_STAGE(i + 4); else CP_COMMIT();

        const uint32_t st = sb + (i % NS) * STG;
        const uint32_t ab = st + AH + a_l;
        const uint32_t bb = st + BH + b_row;
#pragma unroll
        for (int kk = 0; kk < 2; kk++) {
            uint32_t a[4][4], b[2][4];
#pragma unroll
            for (int mi = 0; mi < 4; mi++)
                LDSM4(a[mi], ab + mi * (16 * 80) + kk * 32);
            {
                uint32_t kb = (uint32_t)(kk * 16 * 256);
                LDSM4T(b[0], bb + kb + bcol0);
                LDSM4T(b[1], bb + kb + bcol1);
            }
#pragma unroll
            for (int mi = 0; mi < 4; mi++)
#pragma unroll
                for (int nj = 0; nj < 2; nj++) {
                    MMA_F16(acc[mi][nj * 2 + 0], a[mi], b[nj][0], b[nj][1]);
                    MMA_F16(acc[mi][nj * 2 + 1], a[mi], b[nj][2], b[nj][3]);
                }
        }
    }

    // ---- fused epilogue: relu(+b1) . w2s, reduce, atomicAdd into g_z ----
    const int rr = lane >> 2;
    const int cc = (lane & 3) * 2;
#pragma unroll
    for (int mi = 0; mi < 4; mi++) {
        float pl = 0.f, ph = 0.f;
#pragma unroll
        for (int nj = 0; nj < 4; nj++) {
            int col = n0 + nj * 8 + cc;
            float w0 = w2ss[col], w1v = w2ss[col + 1];
            float bb0 = b1s[col], bb1 = b1s[col + 1];
            pl += fmaxf(acc[mi][nj][0] + bb0, 0.f) * w0
                + fmaxf(acc[mi][nj][1] + bb1, 0.f) * w1v;
            ph += fmaxf(acc[mi][nj][2] + bb0, 0.f) * w0
                + fmaxf(acc[mi][nj][3] + bb1, 0.f) * w1v;
        }
        pl += __shfl_xor_sync(0xffffffffu, pl, 1);
        pl += __shfl_xor_sync(0xffffffffu, pl, 2);
        ph += __shfl_xor_sync(0xffffffffu, ph, 1);
        ph += __shfl_xor_sync(0xffffffffu, ph, 2);
        if ((lane & 3) == 0) {
            int row = cb + m0 + mi * 16 + rr;
            atomicAdd(&g_z[e * CDIM + row], pl);
            atomicAdd(&g_z[e * CDIM + row + 8], ph);
        }
    }
#undef LOAD_STAGE
}

// ---------------- 5. fused combine + log_softmax --------------------------
__global__ void combine_lsm_kernel(float* __restrict__ out) {
    __shared__ float buf[2048];
    __shared__ float sred[512];
    int b = blockIdx.x, t = threadIdx.x;
    for (int i = t; i < 2048; i += 512) {
        int s = b * 2048 + i;
        float v = 0.f;
#pragma unroll
        for (int j = 0; j < 2; j++) {
            int   e = g_dexp[2 * s + j];
            int   p = g_dpos[2 * s + j];
            float g = g_dg  [2 * s + j];
            v += g * (g_z[e * CDIM + p] + g_b2s[e]);
        }
        buf[i] = v;
    }
    __syncthreads();
    float mx = -1e30f;
    for (int i = t; i < 2048; i += 512) mx = fmaxf(mx, buf[i]);
    sred[t] = mx; __syncthreads();
    for (int o = 256; o > 0; o >>= 1) {
        if (t < o) sred[t] = fmaxf(sred[t], sred[t + o]);
        __syncthreads();
    }
    mx = sred[0]; __syncthreads();
    float sm = 0.f;
    for (int i = t; i < 2048; i += 512) sm += expf(buf[i] - mx);
    sred[t] = sm; __syncthreads();
    for (int o = 256; o > 0; o >>= 1) {
        if (t < o) sred[t] += sred[t + o];
        __syncthreads();
    }
    float lse = mx + logf(sred[0]);
    for (int i = t; i < 2048; i += 512)
        out[(size_t)b * 2048 + i] = buf[i] - lse;
}

// ---------------- launch ---------------------------------------------------
extern "C" void kernel_launch(void* const* d_in, const int* in_sizes, int n_in,
                              void* d_out, int out_size) {
    const float* x  = (const float*)d_in[0];
    const float* wg = (const float*)d_in[1];
    const float* w1 = (const float*)d_in[2];
    const float* b1 = (const float*)d_in[3];
    const float* w2 = (const float*)d_in[4];
    const float* b2 = (const float*)d_in[5];
    float* out = (float*)d_out;

    // fork: prep (w1 conversion + w2s/b2s) on side stream, concurrent with
    // routing + scan on the main (capture) stream.
    cudaEventRecord(g_sideinit.e1, (cudaStream_t)0);
    cudaStreamWaitEvent(g_sideinit.s, g_sideinit.e1, 0);
    prep_kernel<<<NW4B + 2049, 256, 0, g_sideinit.s>>>(w1, w2, b2);
    cudaEventRecord(g_sideinit.e2, g_sideinit.s);

    routing_kernel<<<S_TOK / 8, 256>>>(x, wg);
    scan_kernel<<<1, 512>>>();

    // join: GEMM needs both branches
    cudaStreamWaitEvent((cudaStream_t)0, g_sideinit.e2, 0);

    cudaFuncSetAttribute(moe_gemm_fp16,
                         cudaFuncAttributeMaxDynamicSharedMemorySize, GEMM_SMEM);
    moe_gemm_fp16<<<dim3(HDIM / 128, CDIM / 128, EDIM), 256, GEMM_SMEM>>>(b1);

    combine_lsm_kernel<<<4, 512>>>(out);
}

// round 16
// speedup vs baseline: 1.2710x; 1.0154x over previous
#include <cuda_runtime.h>
#include <cuda_fp16.h>
#include <math.h>
#include <stdint.h>

#define S_TOK 8192
#define MDIM  1024
#define HDIM  2048
#define EDIM  8
#define CDIM  2048

// ---------------- scratch (device globals; no allocation) ----------------
__device__ int   g_topi[S_TOK * 2];
__device__ float g_gate[S_TOK * 2];
__device__ int   g_dexp[S_TOK * 2];
__device__ int   g_dpos[S_TOK * 2];
__device__ float g_dg  [S_TOK * 2];
__device__ int   g_src [EDIM * CDIM];
__device__ float g_z   [EDIM * CDIM];
__device__ float g_w2s [EDIM * HDIM];
__device__ float g_b2s [EDIM];
// fp16 copies for MMA
__device__ __half g_xh [(size_t)S_TOK * MDIM];
__device__ __half g_w1h[(size_t)EDIM * MDIM * HDIM];

// ---- side streams + events, created at static-init (host objects) -------
struct SideInit {
    cudaStream_t s1, s2;
    cudaEvent_t e1, e2, e3;
    SideInit() {
        cudaStreamCreateWithFlags(&s1, cudaStreamNonBlocking);
        cudaStreamCreateWithFlags(&s2, cudaStreamNonBlocking);
        cudaEventCreateWithFlags(&e1, cudaEventDisableTiming);
        cudaEventCreateWithFlags(&e2, cudaEventDisableTiming);
        cudaEventCreateWithFlags(&e3, cudaEventDisableTiming);
    }
};
static SideInit g_sideinit;

// ---------------- helpers -------------------------------------------------
__device__ __forceinline__ uint32_t smem_u32(const void* p) {
    uint32_t a;
    asm("{ .reg .u64 t; cvta.to.shared.u64 t, %1; cvt.u32.u64 %0, t; }"
        : "=r"(a) : "l"(p));
    return a;
}
#define CP_ASYNC(saddr, gptr) \
    asm volatile("cp.async.cg.shared.global [%0], [%1], 16;" \
        :: "r"(saddr), "l"(gptr) : "memory")
#define CP_ASYNC_Z(saddr, gptr, srcsz) \
    asm volatile("cp.async.cg.shared.global [%0], [%1], 16, %2;" \
        :: "r"(saddr), "l"(gptr), "r"(srcsz) : "memory")
#define CP_COMMIT() asm volatile("cp.async.commit_group;" ::: "memory")
#define CP_WAIT(n)  asm volatile("cp.async.wait_group %0;" :: "n"(n) : "memory")

#define LDSM4(r, addr) \
    asm volatile("ldmatrix.sync.aligned.m8n8.x4.shared.b16 {%0,%1,%2,%3}, [%4];" \
        : "=r"((r)[0]), "=r"((r)[1]), "=r"((r)[2]), "=r"((r)[3]) : "r"(addr))
#define LDSM4T(r, addr) \
    asm volatile("ldmatrix.sync.aligned.m8n8.x4.trans.shared.b16 {%0,%1,%2,%3}, [%4];" \
        : "=r"((r)[0]), "=r"((r)[1]), "=r"((r)[2]), "=r"((r)[3]) : "r"(addr))
#define MMA_F16(d, a, b0, b1) \
    asm volatile("mma.sync.aligned.m16n8k16.row.col.f32.f16.f16.f32 " \
        "{%0,%1,%2,%3}, {%4,%5,%6,%7}, {%8,%9}, {%0,%1,%2,%3};" \
        : "+f"((d)[0]), "+f"((d)[1]), "+f"((d)[2]), "+f"((d)[3]) \
        : "r"((a)[0]), "r"((a)[1]), "r"((a)[2]), "r"((a)[3]), "r"(b0), "r"(b1))

// ---------------- 1. router (also emits fp16 x) ---------------------------
__global__ void routing_kernel(const float* __restrict__ x,
                               const float* __restrict__ wg) {
    int warp = (blockIdx.x * blockDim.x + threadIdx.x) >> 5;
    int lane = threadIdx.x & 31;
    if (warp >= S_TOK) return;
    const float* xr = x + (size_t)warp * MDIM;
    __half* xh = g_xh + (size_t)warp * MDIM;
    float acc[8];
#pragma unroll
    for (int e = 0; e < 8; e++) acc[e] = 0.f;
    for (int m = lane; m < MDIM; m += 32) {
        float xv = xr[m];
        xh[m] = __float2half_rn(xv);
        const float* wr = wg + m * 8;
        float4 w0 = *(const float4*)(wr);
        float4 w1 = *(const float4*)(wr + 4);
        acc[0] += xv * w0.x; acc[1] += xv * w0.y;
        acc[2] += xv * w0.z; acc[3] += xv * w0.w;
        acc[4] += xv * w1.x; acc[5] += xv * w1.y;
        acc[6] += xv * w1.z; acc[7] += xv * w1.w;
    }
#pragma unroll
    for (int off = 16; off > 0; off >>= 1)
#pragma unroll
        for (int e = 0; e < 8; e++)
            acc[e] += __shfl_down_sync(0xffffffffu, acc[e], off);
    if (lane == 0) {
        float mx = acc[0];
#pragma unroll
        for (int e = 1; e < 8; e++) mx = fmaxf(mx, acc[e]);
        float sc[8], s = 0.f;
#pragma unroll
        for (int e = 0; e < 8; e++) { sc[e] = expf(acc[e] - mx); s += sc[e]; }
        float inv = 1.f / s;
#pragma unroll
        for (int e = 0; e < 8; e++) sc[e] *= inv;
        int i0 = 0;
#pragma unroll
        for (int e = 1; e < 8; e++) if (sc[e] > sc[i0]) i0 = e;
        int i1 = -1;
#pragma unroll
        for (int e = 0; e < 8; e++) {
            if (e == i0) continue;
            if (i1 < 0 || sc[e] > sc[i1]) i1 = e;
        }
        float v0 = sc[i0], v1 = sc[i1];
        float den = 1.f / (v0 + v1 + 1e-9f);
        g_topi[warp * 2 + 0] = i0;
        g_topi[warp * 2 + 1] = i1;
        g_gate[warp * 2 + 0] = v0 * den;
        g_gate[warp * 2 + 1] = v1 * den;
    }
}

// ---------------- 2. ordered scan (512 thr, warp-parallel bin scans) ------
__global__ void scan_kernel() {
    __shared__ int h0[512][9];
    __shared__ int h1[512][9];
    __shared__ int tot0s[8];
    int t = threadIdx.x;
    for (int i = t; i < EDIM * CDIM; i += 512) { g_src[i] = -1; g_z[i] = 0.f; }

    int c0[8], c1[8];
#pragma unroll
    for (int e = 0; e < 8; e++) { c0[e] = 0; c1[e] = 0; }
    int base = t * 16;
    for (int k = 0; k < 16; k++) {
        int s = base + k;
        c0[g_topi[2 * s + 0]]++;
        c1[g_topi[2 * s + 1]]++;
    }
#pragma unroll
    for (int e = 0; e < 8; e++) { h0[t][e] = c0[e]; h1[t][e] = c1[e]; }
    __syncthreads();

    int wid = t >> 5, lane = t & 31;
    if (wid < 16) {
        int e = wid & 7, which = wid >> 3;
        int vals[16], run = 0;
#pragma unroll
        for (int j = 0; j < 16; j++) {
            int v = which ? h1[lane * 16 + j][e] : h0[lane * 16 + j][e];
            vals[j] = run; run += v;
        }
        int tot = run;
#pragma unroll
        for (int off = 1; off < 32; off <<= 1) {
            int n = __shfl_up_sync(0xffffffffu, tot, off);
            if (lane >= off) tot += n;
        }
        int excl = tot - run;
#pragma unroll
        for (int j = 0; j < 16; j++) {
            if (which) h1[lane * 16 + j][e] = vals[j] + excl;
            else       h0[lane * 16 + j][e] = vals[j] + excl;
        }
        if (lane == 31 && which == 0) tot0s[e] = tot;
    }
    __syncthreads();

#pragma unroll
    for (int e = 0; e < 8; e++) { c0[e] = h0[t][e]; c1[e] = h1[t][e] + tot0s[e]; }
    for (int k = 0; k < 16; k++) {
        int s = base + k;
        {
            int e = g_topi[2 * s + 0];
            int pos = c0[e]++;
            int keep = (pos < CDIM);
            int posc = keep ? pos : (CDIM - 1);
            g_dexp[2 * s + 0] = e;
            g_dpos[2 * s + 0] = posc;
            g_dg  [2 * s + 0] = keep ? g_gate[2 * s + 0] : 0.f;
            if (keep) g_src[e * CDIM + posc] = s;
        }
        {
            int e = g_topi[2 * s + 1];
            int pos = c1[e]++;
            int keep = (pos < CDIM);
            int posc = keep ? pos : (CDIM - 1);
            g_dexp[2 * s + 1] = e;
            g_dpos[2 * s + 1] = posc;
            g_dg  [2 * s + 1] = keep ? g_gate[2 * s + 1] : 0.f;
            if (keep) g_src[e * CDIM + posc] = s;
        }
    }
}

// ---------------- 3a. prep_w1: w1 -> fp16 (2x MLP) ------------------------
#define NW4   (EDIM * MDIM * HDIM / 4)
#define NW4H  (NW4 / 2)
#define NW4B  (NW4H / 256)
__global__ void prep_w1_kernel(const float* __restrict__ w1) {
    int i = blockIdx.x * 256 + threadIdx.x;
    float4 v0 = ((const float4*)w1)[i];
    float4 v1 = ((const float4*)w1)[i + NW4H];
    __half2 a01 = __floats2half2_rn(v0.x, v0.y);
    __half2 a23 = __floats2half2_rn(v0.z, v0.w);
    __half2 b01 = __floats2half2_rn(v1.x, v1.y);
    __half2 b23 = __floats2half2_rn(v1.z, v1.w);
    ((uint2*)g_w1h)[i]        = make_uint2(*(uint32_t*)&a01, *(uint32_t*)&a23);
    ((uint2*)g_w1h)[i + NW4H] = make_uint2(*(uint32_t*)&b01, *(uint32_t*)&b23);
}

// ---------------- 3b. prep_w2s: w2s / b2s reductions ----------------------
__global__ void prep_w2s_kernel(const float* __restrict__ w2,
                                const float* __restrict__ b2) {
    int warp = blockIdx.x * 8 + (threadIdx.x >> 5);
    int lane = threadIdx.x & 31;
    if (warp < EDIM * HDIM) {
        const float4* r = (const float4*)(w2 + (size_t)warp * MDIM);
        float s = 0.f;
        for (int m = lane; m < MDIM / 4; m += 32) {
            float4 v = r[m];
            s += v.x + v.y + v.z + v.w;
        }
#pragma unroll
        for (int off = 16; off > 0; off >>= 1) s += __shfl_down_sync(0xffffffffu, s, off);
        if (lane == 0) g_w2s[warp] = s;
    } else if (warp < EDIM * HDIM + EDIM) {
        int e = warp - EDIM * HDIM;
        const float4* r = (const float4*)(b2 + (size_t)e * MDIM);
        float s = 0.f;
        for (int m = lane; m < MDIM / 4; m += 32) {
            float4 v = r[m];
            s += v.x + v.y + v.z + v.w;
        }
#pragma unroll
        for (int off = 16; off > 0; off >>= 1) s += __shfl_down_sync(0xffffffffu, s, off);
        if (lane == 0) g_b2s[e] = s;
    }
}

// ---------------- 4. fp16 mma.sync fused GEMM -----------------------------
// CTA tile 128(C) x 128(H), BK=32, NS=6, CP_WAIT+barrier every 2 iters only
// (even-iter wait completes groups i AND i+1; odd iters run stall-free),
// 256 thr, 2 CTAs/SM. A rows 80B pad; B k-rows 256B, XOR-8 swizzle.
#define NS   6
#define AH   0
#define BH   10240
#define STG  18432
#define GEMM_SMEM (NS * STG)

__global__ __launch_bounds__(256, 2)
void moe_gemm_fp16(const float* __restrict__ b1) {
    extern __shared__ char smem[];
    __shared__ int   rowsrc[128];
    __shared__ float b1s[128];
    __shared__ float w2ss[128];

    const int tid  = threadIdx.x;
    const int lane = tid & 31;
    const int wid  = tid >> 5;
    const int e  = blockIdx.z;
    const int cb = blockIdx.y * 128;
    const int nb = blockIdx.x * 128;

    if (tid < 128) {
        rowsrc[tid] = g_src[e * CDIM + cb + tid];
        b1s[tid]  = b1[e * HDIM + nb + tid];
        w2ss[tid] = g_w2s[e * HDIM + nb + tid];
    }
    __syncthreads();
    const uint32_t sb = smem_u32(smem);

    // ---- cp.async assignments ----
    const int ar = tid >> 2, au = tid & 3;
    const int s0 = rowsrc[ar], s1 = rowsrc[ar + 64];
    const uint32_t sz0 = (s0 >= 0) ? 16u : 0u;
    const uint32_t sz1 = (s1 >= 0) ? 16u : 0u;
    const char* gx0 = (const char*)g_xh + ((size_t)(s0 < 0 ? 0 : s0) * MDIM + au * 8) * 2;
    const char* gx1 = (const char*)g_xh + ((size_t)(s1 < 0 ? 0 : s1) * MDIM + au * 8) * 2;
    const uint32_t aoff0 = (uint32_t)(ar * 80 + au * 16);
    const uint32_t aoff1 = (uint32_t)((ar + 64) * 80 + au * 16);
    const int br = tid >> 4, bu = tid & 15;
    const char* gb = (const char*)g_w1h + (((size_t)e * MDIM) * HDIM + nb + bu * 8) * 2;
    const uint32_t sB0 = (uint32_t)(br * 256 + ((bu ^ (br & 7)) << 4));
    const uint32_t sB1 = sB0 + 16 * 256;

#define LOAD_STAGE(i) do {                                                    \
    const int _k0 = (i) * 32;                                                 \
    const uint32_t _st = sb + ((i) % NS) * STG;                               \
    CP_ASYNC_Z(_st + AH + aoff0, gx0 + _k0 * 2, sz0);                         \
    CP_ASYNC_Z(_st + AH + aoff1, gx1 + _k0 * 2, sz1);                         \
    const size_t _g = (size_t)(_k0 + br) * (HDIM * 2);                        \
    CP_ASYNC(_st + BH + sB0, gb + _g);                                        \
    CP_ASYNC(_st + BH + sB1, gb + _g + (size_t)16 * HDIM * 2);                \
    CP_COMMIT();                                                              \
} while (0)

    // ---- mma thread geometry: 8 warps = 2 (m) x 4 (n), warp tile 64x32 ----
    const int m0 = (wid & 1) * 64;
    const int n0 = (wid >> 1) * 32;
    const uint32_t a_l = (uint32_t)((m0 + (lane & 15)) * 80 + ((lane >> 4) & 1) * 16);
    const int krow = lane & 15;
    const int un0  = (n0 >> 3) + (lane >> 4);
    const uint32_t b_row = (uint32_t)(krow * 256);
    const uint32_t bcol0 = (uint32_t)(((un0 + 0) ^ (krow & 7)) << 4);
    const uint32_t bcol1 = (uint32_t)(((un0 + 2) ^ (krow & 7)) << 4);

    float acc[4][4][4];
#pragma unroll
    for (int mi = 0; mi < 4; mi++)
#pragma unroll
        for (int nj = 0; nj < 4; nj++)
#pragma unroll
            for (int q = 0; q < 4; q++) acc[mi][nj][q] = 0.f;

    LOAD_STAGE(0);
    LOAD_STAGE(1);
    LOAD_STAGE(2);
    LOAD_STAGE(3);

#pragma unroll 2
    for (int i = 0; i < 32; i++) {
        // Even iters: wait (completes groups i and i+1) + publish barrier.
        // Odd iters: stage i already complete and published; no stall point.
        // Overwrite guard: LOAD_STAGE(i+4) writes the stage consumed at
        // iter i-2 (NS=6); barrier every 2 bounds warp skew < 2. Safe.
        if ((i & 1) == 0) { CP_WAIT(2); __syncthreads(); }
        if (i + 4 < 32) LOAD_STAGE(i + 4); else CP_COMMIT();

        const uint32_t st = sb + (i % NS) * STG;
        const uint32_t ab = st + AH + a_l;
        const uint32_t bb = st + BH + b_row;
#pragma unroll
        for (int kk = 0; kk < 2; kk++) {
            uint32_t a[4][4], b[2][4];
#pragma unroll
            for (int mi = 0; mi < 4; mi++)
                LDSM4(a[mi], ab + mi * (16 * 80) + kk * 32);
            {
                uint32_t kb = (uint32_t)(kk * 16 * 256);
                LDSM4T(b[0], bb + kb + bcol0);
                LDSM4T(b[1], bb + kb + bcol1);
            }
#pragma unroll
            for (int mi = 0; mi < 4; mi++)
#pragma unroll
                for (int nj = 0; nj < 2; nj++) {
                    MMA_F16(acc[mi][nj * 2 + 0], a[mi], b[nj][0], b[nj][1]);
                    MMA_F16(acc[mi][nj * 2 + 1], a[mi], b[nj][2], b[nj][3]);
                }
        }
    }

    // ---- fused epilogue: relu(+b1) . w2s, reduce, atomicAdd into g_z ----
    const int rr = lane >> 2;
    const int cc = (lane & 3) * 2;
#pragma unroll
    for (int mi = 0; mi < 4; mi++) {
        float pl = 0.f, ph = 0.f;
#pragma unroll
        for (int nj = 0; nj < 4; nj++) {
            int col = n0 + nj * 8 + cc;
            float w0 = w2ss[col], w1v = w2ss[col + 1];
            float bb0 = b1s[col], bb1 = b1s[col + 1];
            pl += fmaxf(acc[mi][nj][0] + bb0, 0.f) * w0
                + fmaxf(acc[mi][nj][1] + bb1, 0.f) * w1v;
            ph += fmaxf(acc[mi][nj][2] + bb0, 0.f) * w0
                + fmaxf(acc[mi][nj][3] + bb1, 0.f) * w1v;
        }
        pl += __shfl_xor_sync(0xffffffffu, pl, 1);
        pl += __shfl_xor_sync(0xffffffffu, pl, 2);
        ph += __shfl_xor_sync(0xffffffffu, ph, 1);
        ph += __shfl_xor_sync(0xffffffffu, ph, 2);
        if ((lane & 3) == 0) {
            int row = cb + m0 + mi * 16 + rr;
            atomicAdd(&g_z[e * CDIM + row], pl);
            atomicAdd(&g_z[e * CDIM + row + 8], ph);
        }
    }
#undef LOAD_STAGE
}

// ---------------- 5. fused combine + log_softmax --------------------------
__global__ void combine_lsm_kernel(float* __restrict__ out) {
    __shared__ float buf[2048];
    __shared__ float sred[512];
    int b = blockIdx.x, t = threadIdx.x;
    for (int i = t; i < 2048; i += 512) {
        int s = b * 2048 + i;
        float v = 0.f;
#pragma unroll
        for (int j = 0; j < 2; j++) {
            int   e = g_dexp[2 * s + j];
            int   p = g_dpos[2 * s + j];
            float g = g_dg  [2 * s + j];
            v += g * (g_z[e * CDIM + p] + g_b2s[e]);
        }
        buf[i] = v;
    }
    __syncthreads();
    float mx = -1e30f;
    for (int i = t; i < 2048; i += 512) mx = fmaxf(mx, buf[i]);
    sred[t] = mx; __syncthreads();
    for (int o = 256; o > 0; o >>= 1) {
        if (t < o) sred[t] = fmaxf(sred[t], sred[t + o]);
        __syncthreads();
    }
    mx = sred[0]; __syncthreads();
    float sm = 0.f;
    for (int i = t; i < 2048; i += 512) sm += expf(buf[i] - mx);
    sred[t] = sm; __syncthreads();
    for (int o = 256; o > 0; o >>= 1) {
        if (t < o) sred[t] += sred[t + o];
        __syncthreads();
    }
    float lse = mx + logf(sred[0]);
    for (int i = t; i < 2048; i += 512)
        out[(size_t)b * 2048 + i] = buf[i] - lse;
}

// ---------------- launch ---------------------------------------------------
extern "C" void kernel_launch(void* const* d_in, const int* in_sizes, int n_in,
                              void* d_out, int out_size) {
    const float* x  = (const float*)d_in[0];
    const float* wg = (const float*)d_in[1];
    const float* w1 = (const float*)d_in[2];
    const float* b1 = (const float*)d_in[3];
    const float* w2 = (const float*)d_in[4];
    const float* b2 = (const float*)d_in[5];
    float* out = (float*)d_out;

    // 3-way fork: prep_w1 || prep_w2s || (routing -> scan)
    cudaEventRecord(g_sideinit.e1, (cudaStream_t)0);
    cudaStreamWaitEvent(g_sideinit.s1, g_sideinit.e1, 0);
    cudaStreamWaitEvent(g_sideinit.s2, g_sideinit.e1, 0);
    prep_w1_kernel<<<NW4B, 256, 0, g_sideinit.s1>>>(w1);
    cudaEventRecord(g_sideinit.e2, g_sideinit.s1);
    prep_w2s_kernel<<<2049, 256, 0, g_sideinit.s2>>>(w2, b2);
    cudaEventRecord(g_sideinit.e3, g_sideinit.s2);

    routing_kernel<<<S_TOK / 8, 256>>>(x, wg);
    scan_kernel<<<1, 512>>>();

    // join: GEMM needs all branches
    cudaStreamWaitEvent((cudaStream_t)0, g_sideinit.e2, 0);
    cudaStreamWaitEvent((cudaStream_t)0, g_sideinit.e3, 0);

    cudaFuncSetAttribute(moe_gemm_fp16,
                         cudaFuncAttributeMaxDynamicSharedMemorySize, GEMM_SMEM);
    moe_gemm_fp16<<<dim3(HDIM / 128, CDIM / 128, EDIM), 256, GEMM_SMEM>>>(b1);

    combine_lsm_kernel<<<4, 512>>>(out);
}